// round 13
// baseline (speedup 1.0000x reference)
#include <cuda_runtime.h>
#include <cuda_fp16.h>
#include <cstdint>

#define N_TOK 16384
#define DIN   768
#define NEXP  8
#define HDIM  2048

#define BM 128
#define BN 256
#define BK 64
#define PITCH 72              // smem row pitch in halfs (144B = 9*16B, conflict-free)
#define PITCHB (PITCH * 2)    // 144 bytes

#define A_BYTES (BM * PITCHB)               // 18432
#define B_BYTES (BN * PITCHB)               // 36864
#define STAGE_BYTES (A_BYTES + B_BYTES)     // 55296
#define STAGES 3
#define SMEM_BYTES (STAGES * STAGE_BYTES)   // 165888

// ---------------- device scratch (referenced ONLY from device code) ----------------
__device__ __align__(256) int    g_count[NEXP];
__device__ __align__(256) int    g_list[NEXP * N_TOK];
__device__ __align__(256) int    g_expert[N_TOK];
__device__ __align__(256) float  g_prob[N_TOK];
__device__ __align__(256) __half g_xh[(size_t)N_TOK * DIN];
__device__ __align__(256) __half g_encT[(size_t)NEXP * HDIM * DIN];  // [e][n][k]
__device__ __align__(256) __half g_decT[(size_t)NEXP * DIN * HDIM];  // [e][n][k]
__device__ __align__(256) __half g_latent[(size_t)N_TOK * HDIM];

// ---------------- asm helpers ----------------
__device__ __forceinline__ uint32_t smem_u32(const void* p) {
    uint32_t a;
    asm("{ .reg .u64 t; cvta.to.shared.u64 t, %1; cvt.u32.u64 %0, t; }" : "=r"(a) : "l"(p));
    return a;
}
#define CP16(dst, src) \
    asm volatile("cp.async.cg.shared.global [%0], [%1], 16;" :: "r"(dst), "l"(src) : "memory")
#define CP16Z(dst, src, sz) \
    asm volatile("cp.async.cg.shared.global [%0], [%1], 16, %2;" :: "r"(dst), "l"(src), "r"(sz) : "memory")
#define CP_COMMIT() asm volatile("cp.async.commit_group;" ::: "memory")
#define CP_WAIT(n)  asm volatile("cp.async.wait_group %0;" :: "n"(n) : "memory")

__device__ __forceinline__ void ldsm4(uint32_t& r0, uint32_t& r1, uint32_t& r2, uint32_t& r3,
                                      uint32_t addr) {
    asm volatile("ldmatrix.sync.aligned.m8n8.x4.shared.b16 {%0,%1,%2,%3}, [%4];"
                 : "=r"(r0), "=r"(r1), "=r"(r2), "=r"(r3) : "r"(addr));
}
__device__ __forceinline__ void mma_f16(float& c0, float& c1, float& c2, float& c3,
                                        uint32_t a0, uint32_t a1, uint32_t a2, uint32_t a3,
                                        uint32_t b0, uint32_t b1) {
    asm volatile("mma.sync.aligned.m16n8k16.row.col.f32.f16.f16.f32 "
                 "{%0,%1,%2,%3}, {%4,%5,%6,%7}, {%8,%9}, {%0,%1,%2,%3};\n"
                 : "+f"(c0), "+f"(c1), "+f"(c2), "+f"(c3)
                 : "r"(a0), "r"(a1), "r"(a2), "r"(a3), "r"(b0), "r"(b1));
}

// ---------------- prologue kernels ----------------
// router: logits, max-prob, expert idx; ALSO zeroes counts (block 0) and writes g_xh.
__global__ void router_kernel(const float* __restrict__ x,
                              const float* __restrict__ router_b,
                              const float* __restrict__ router) {
    if (blockIdx.x == 0 && threadIdx.x < NEXP) g_count[threadIdx.x] = 0;
    const int warp = threadIdx.x >> 5, lane = threadIdx.x & 31;
    const int tok = blockIdx.x * 8 + warp;
    float acc[8];
#pragma unroll
    for (int e = 0; e < 8; e++) acc[e] = 0.f;
    const float* xr = x + (size_t)tok * DIN;
    __half* xh = g_xh + (size_t)tok * DIN;
    for (int d = lane; d < DIN; d += 32) {
        const float xraw = xr[d];
        xh[d] = __float2half_rn(xraw);            // fp16 conversion fused here
        float xv = xraw - router_b[d];
        float4 ra = *(const float4*)(router + d * 8);
        float4 rb = *(const float4*)(router + d * 8 + 4);
        acc[0] += xv * ra.x; acc[1] += xv * ra.y;
        acc[2] += xv * ra.z; acc[3] += xv * ra.w;
        acc[4] += xv * rb.x; acc[5] += xv * rb.y;
        acc[6] += xv * rb.z; acc[7] += xv * rb.w;
    }
#pragma unroll
    for (int e = 0; e < 8; e++) {
#pragma unroll
        for (int off = 16; off > 0; off >>= 1)
            acc[e] += __shfl_xor_sync(0xffffffffu, acc[e], off);
    }
    if (lane == 0) {
        float m = acc[0]; int idx = 0;
#pragma unroll
        for (int e = 1; e < 8; e++) if (acc[e] > m) { m = acc[e]; idx = e; }
        float s = 0.f;
#pragma unroll
        for (int e = 0; e < 8; e++) s += expf(acc[e] - m);
        g_expert[tok] = idx;
        g_prob[tok] = 1.f / s;
    }
}

__global__ void build_lists_kernel() {
    const int t = blockIdx.x * blockDim.x + threadIdx.x;
    if (t >= N_TOK) return;
    const int e = g_expert[t];
    const int pos = atomicAdd(&g_count[e], 1);
    g_list[e * N_TOK + pos] = t;
}

// in: [e][K][N] fp32 -> g_encT/g_decT: [e][N][K] fp16 (output symbol chosen IN KERNEL)
template<bool ENC>
__global__ void transpose_cvt_kernel(const float* __restrict__ in, int K, int N) {
    __half* outBase = ENC ? g_encT : g_decT;
    __shared__ __half tile[32][33];
    const float* ine = in + (size_t)blockIdx.z * K * N;
    __half* oute = outBase + (size_t)blockIdx.z * (size_t)K * N;
    const int n0 = blockIdx.x * 32, k0 = blockIdx.y * 32;
    const int tx = threadIdx.x, ty = threadIdx.y;
#pragma unroll
    for (int j = 0; j < 32; j += 8)
        tile[ty + j][tx] = __float2half_rn(ine[(size_t)(k0 + ty + j) * N + n0 + tx]);
    __syncthreads();
#pragma unroll
    for (int j = 0; j < 32; j += 8)
        oute[(size_t)(n0 + ty + j) * K + k0 + tx] = tile[tx][ty + j];
}

// ---------------- fp16 gather-GEMM: 128x256, 64x64 warp tiles, BK=64, 3-stage cp.async ----------------
template<int KTOT, bool G1>
__global__ void __launch_bounds__(256) sae_gemm_kernel(
    const float* __restrict__ pre_b, float* __restrict__ out)
{
    const int e = blockIdx.z;
    const int cnt = g_count[e];
    const int mBase = blockIdx.y * BM;
    if (mBase >= cnt) return;
    const int nBase = blockIdx.x * BN;
    const int* list = g_list + e * N_TOK;

    const __half* Asrc = G1 ? g_xh : g_latent;
    const __half* WT = (G1 ? g_encT : g_decT) + (size_t)e * (size_t)HDIM * DIN;

    extern __shared__ __align__(128) char smem[];
    const uint32_t sb = smem_u32(smem);

    const int tid = threadIdx.x, lane = tid & 31, warp = tid >> 5;
    const int wm = (warp >> 2) * 64, wn = (warp & 3) * 64;
    const int grp = lane >> 2, tig = lane & 3;

    // A staging: 2 threads per row, 64B each
    const int aRow = tid >> 1, sHalf = tid & 1;
    const int tokS = (mBase + aRow < cnt) ? list[mBase + aRow] : -1;
    const char* aSrcRow = (const char*)(Asrc + (size_t)(tokS >= 0 ? tokS : 0) * KTOT);
    const uint32_t aSz = (tokS >= 0) ? 16u : 0u;
    // B staging: 1 thread per n row, 128B
    const char* bSrcRow = (const char*)(WT + (size_t)(nBase + tid) * KTOT);

    const uint32_t aDstOff = (uint32_t)(aRow * PITCHB + sHalf * 64);
    const uint32_t bDstOff = (uint32_t)(A_BYTES + tid * PITCHB);

    auto issue = [&](int c) {
        int st = c % STAGES;
        const uint32_t base = sb + (uint32_t)st * STAGE_BYTES;
        const char* as = aSrcRow + c * 128 + sHalf * 64;
        const uint32_t ad = base + aDstOff;
        CP16Z(ad,      as,      aSz);
        CP16Z(ad + 16, as + 16, aSz);
        CP16Z(ad + 32, as + 32, aSz);
        CP16Z(ad + 48, as + 48, aSz);
        const char* bs = bSrcRow + c * 128;
        const uint32_t bd = base + bDstOff;
#pragma unroll
        for (int j = 0; j < 8; j++) CP16(bd + j * 16, bs + j * 16);
    };

    // ldmatrix per-thread address components (bytes, within stage)
    const uint32_t aLdsm = (uint32_t)((wm + (lane & 15)) * PITCHB + (lane >> 4) * 16);
    const uint32_t bLdsm = (uint32_t)(A_BYTES
                         + (wn + ((lane >> 4) << 3) + (lane & 7)) * PITCHB
                         + ((lane >> 3) & 1) * 16);

    float c[4][8][4];
#pragma unroll
    for (int mi = 0; mi < 4; mi++)
#pragma unroll
        for (int ni = 0; ni < 8; ni++)
#pragma unroll
            for (int j = 0; j < 4; j++) c[mi][ni][j] = 0.f;

    const int KT = KTOT / BK;      // G1: 12, G2: 32
#pragma unroll
    for (int s = 0; s < STAGES - 1; s++) {
        if (s < KT) issue(s);
        CP_COMMIT();
    }

    for (int kt = 0; kt < KT; ++kt) {
        CP_WAIT(STAGES - 2);
        __syncthreads();

        const uint32_t stageB = sb + (uint32_t)(kt % STAGES) * STAGE_BYTES;

        uint32_t aF[2][4][4], bF[2][8][2];

        // preload k-half 0 fragments
#pragma unroll
        for (int mi = 0; mi < 4; mi++)
            ldsm4(aF[0][mi][0], aF[0][mi][1], aF[0][mi][2], aF[0][mi][3],
                  stageB + aLdsm + (uint32_t)(mi * 16 * PITCHB));
#pragma unroll
        for (int p = 0; p < 4; p++)
            ldsm4(bF[0][2 * p][0], bF[0][2 * p][1], bF[0][2 * p + 1][0], bF[0][2 * p + 1][1],
                  stageB + bLdsm + (uint32_t)(p * 16 * PITCHB));

        // next chunk's global loads — LSU pipe, overlaps below
        if (kt + STAGES - 1 < KT) issue(kt + STAGES - 1);
        CP_COMMIT();

#pragma unroll
        for (int kk = 0; kk < 4; kk++) {
            const int cur = kk & 1, nxt = cur ^ 1;
            if (kk < 3) {
                const uint32_t kOff = (uint32_t)((kk + 1) * 32);
#pragma unroll
                for (int mi = 0; mi < 4; mi++)
                    ldsm4(aF[nxt][mi][0], aF[nxt][mi][1], aF[nxt][mi][2], aF[nxt][mi][3],
                          stageB + aLdsm + (uint32_t)(mi * 16 * PITCHB) + kOff);
#pragma unroll
                for (int p = 0; p < 4; p++)
                    ldsm4(bF[nxt][2 * p][0], bF[nxt][2 * p][1],
                          bF[nxt][2 * p + 1][0], bF[nxt][2 * p + 1][1],
                          stageB + bLdsm + (uint32_t)(p * 16 * PITCHB) + kOff);
            }
#pragma unroll
            for (int mi = 0; mi < 4; mi++)
#pragma unroll
                for (int ni = 0; ni < 8; ni++)
                    mma_f16(c[mi][ni][0], c[mi][ni][1], c[mi][ni][2], c[mi][ni][3],
                            aF[cur][mi][0], aF[cur][mi][1], aF[cur][mi][2], aF[cur][mi][3],
                            bF[cur][ni][0], bF[cur][ni][1]);
        }
    }

    // ---- epilogue ----
#pragma unroll
    for (int mi = 0; mi < 4; mi++) {
        const int r0 = mBase + wm + mi * 16 + grp;
        const int r1 = r0 + 8;
        const int t0 = (r0 < cnt) ? list[r0] : -1;
        const int t1 = (r1 < cnt) ? list[r1] : -1;
        float p0 = 0.f, p1 = 0.f;
        if (!G1) {
            p0 = (t0 >= 0) ? g_prob[t0] : 0.f;
            p1 = (t1 >= 0) ? g_prob[t1] : 0.f;
        }
#pragma unroll
        for (int ni = 0; ni < 8; ni++) {
            const int col = nBase + wn + ni * 8 + tig * 2;
            if (G1) {
                if (t0 >= 0) {
                    __half2 v = __floats2half2_rn(fmaxf(c[mi][ni][0], 0.f), fmaxf(c[mi][ni][1], 0.f));
                    *(__half2*)(g_latent + (size_t)t0 * HDIM + col) = v;
                }
                if (t1 >= 0) {
                    __half2 v = __floats2half2_rn(fmaxf(c[mi][ni][2], 0.f), fmaxf(c[mi][ni][3], 0.f));
                    *(__half2*)(g_latent + (size_t)t1 * HDIM + col) = v;
                }
            } else {
                const float pb0 = __ldg(pre_b + col), pb1 = __ldg(pre_b + col + 1);
                if (t0 >= 0) {
                    float2 v = make_float2(p0 * c[mi][ni][0] + pb0, p0 * c[mi][ni][1] + pb1);
                    *(float2*)(out + (size_t)t0 * DIN + col) = v;
                }
                if (t1 >= 0) {
                    float2 v = make_float2(p1 * c[mi][ni][2] + pb0, p1 * c[mi][ni][3] + pb1);
                    *(float2*)(out + (size_t)t1 * DIN + col) = v;
                }
            }
        }
    }
}

// ---------------- launcher ----------------
extern "C" void kernel_launch(void* const* d_in, const int* in_sizes, int n_in,
                              void* d_out, int out_size) {
    const float* x        = (const float*)d_in[0];
    const float* pre_b    = (const float*)d_in[1];
    const float* enc      = (const float*)d_in[2];
    const float* dec      = (const float*)d_in[3];
    const float* router_b = (const float*)d_in[4];
    const float* router   = (const float*)d_in[5];
    float* out = (float*)d_out;

    cudaFuncSetAttribute(sae_gemm_kernel<DIN, true>,
                         cudaFuncAttributeMaxDynamicSharedMemorySize, SMEM_BYTES);
    cudaFuncSetAttribute(sae_gemm_kernel<HDIM, false>,
                         cudaFuncAttributeMaxDynamicSharedMemorySize, SMEM_BYTES);

    dim3 tb(32, 8);
    // Launch order puts gemm1 in the ncu capture slot (#4).
    router_kernel<<<N_TOK / 8, 256>>>(x, router_b, router);                     // 1
    build_lists_kernel<<<N_TOK / 256, 256>>>();                                 // 2
    transpose_cvt_kernel<true ><<<dim3(HDIM / 32, DIN / 32, NEXP), tb>>>(enc, DIN, HDIM);  // 3
    dim3 g1(HDIM / BN, N_TOK / BM, NEXP);
    sae_gemm_kernel<DIN, true><<<g1, 256, SMEM_BYTES>>>(pre_b, out);            // 4 (profiled)
    transpose_cvt_kernel<false><<<dim3(DIN / 32, HDIM / 32, NEXP), tb>>>(dec, HDIM, DIN);  // 5
    dim3 g2(DIN / BN, N_TOK / BM, NEXP);
    sae_gemm_kernel<HDIM, false><<<g2, 256, SMEM_BYTES>>>(pre_b, out);          // 6
}

// round 14
// speedup vs baseline: 1.1324x; 1.1324x over previous
#include <cuda_runtime.h>
#include <cuda_fp16.h>
#include <cstdint>

#define N_TOK 16384
#define DIN   768
#define NEXP  8
#define HDIM  2048

#define BM 128
#define BN 128
#define BK 32
#define PITCH 40              // smem row pitch in halfs
#define PITCHB (PITCH * 2)    // 80 bytes

#define A_BYTES (BM * PITCHB)               // 10240
#define B_BYTES (BN * PITCHB)               // 10240
#define STAGE_BYTES (A_BYTES + B_BYTES)     // 20480
#define STAGES 3
#define SMEM_BYTES (STAGES * STAGE_BYTES)   // 61440 per CTA (x2 CTAs = 120KB/SM)

// ---------------- device scratch (referenced ONLY from device code) ----------------
__device__ __align__(256) int    g_count[NEXP];
__device__ __align__(256) int    g_list[NEXP * N_TOK];
__device__ __align__(256) int    g_expert[N_TOK];
__device__ __align__(256) float  g_prob[N_TOK];
__device__ __align__(256) __half g_xh[(size_t)N_TOK * DIN];
__device__ __align__(256) __half g_encT[(size_t)NEXP * HDIM * DIN];  // [e][n][k]
__device__ __align__(256) __half g_decT[(size_t)NEXP * DIN * HDIM];  // [e][n][k]
__device__ __align__(256) __half g_latent[(size_t)N_TOK * HDIM];

// ---------------- asm helpers ----------------
__device__ __forceinline__ uint32_t smem_u32(const void* p) {
    uint32_t a;
    asm("{ .reg .u64 t; cvta.to.shared.u64 t, %1; cvt.u32.u64 %0, t; }" : "=r"(a) : "l"(p));
    return a;
}
#define CP16(dst, src) \
    asm volatile("cp.async.cg.shared.global [%0], [%1], 16;" :: "r"(dst), "l"(src) : "memory")
#define CP16Z(dst, src, sz) \
    asm volatile("cp.async.cg.shared.global [%0], [%1], 16, %2;" :: "r"(dst), "l"(src), "r"(sz) : "memory")
#define CP_COMMIT() asm volatile("cp.async.commit_group;" ::: "memory")
#define CP_WAIT(n)  asm volatile("cp.async.wait_group %0;" :: "n"(n) : "memory")

__device__ __forceinline__ void ldsm4(uint32_t& r0, uint32_t& r1, uint32_t& r2, uint32_t& r3,
                                      uint32_t addr) {
    asm volatile("ldmatrix.sync.aligned.m8n8.x4.shared.b16 {%0,%1,%2,%3}, [%4];"
                 : "=r"(r0), "=r"(r1), "=r"(r2), "=r"(r3) : "r"(addr));
}
__device__ __forceinline__ void mma_f16(float& c0, float& c1, float& c2, float& c3,
                                        uint32_t a0, uint32_t a1, uint32_t a2, uint32_t a3,
                                        uint32_t b0, uint32_t b1) {
    asm volatile("mma.sync.aligned.m16n8k16.row.col.f32.f16.f16.f32 "
                 "{%0,%1,%2,%3}, {%4,%5,%6,%7}, {%8,%9}, {%0,%1,%2,%3};\n"
                 : "+f"(c0), "+f"(c1), "+f"(c2), "+f"(c3)
                 : "r"(a0), "r"(a1), "r"(a2), "r"(a3), "r"(b0), "r"(b1));
}

// ---------------- prologue kernels ----------------
__global__ void router_kernel(const float* __restrict__ x,
                              const float* __restrict__ router_b,
                              const float* __restrict__ router) {
    if (blockIdx.x == 0 && threadIdx.x < NEXP) g_count[threadIdx.x] = 0;
    const int warp = threadIdx.x >> 5, lane = threadIdx.x & 31;
    const int tok = blockIdx.x * 8 + warp;
    float acc[8];
#pragma unroll
    for (int e = 0; e < 8; e++) acc[e] = 0.f;
    const float* xr = x + (size_t)tok * DIN;
    __half* xh = g_xh + (size_t)tok * DIN;
    for (int d = lane; d < DIN; d += 32) {
        const float xraw = xr[d];
        xh[d] = __float2half_rn(xraw);
        float xv = xraw - router_b[d];
        float4 ra = *(const float4*)(router + d * 8);
        float4 rb = *(const float4*)(router + d * 8 + 4);
        acc[0] += xv * ra.x; acc[1] += xv * ra.y;
        acc[2] += xv * ra.z; acc[3] += xv * ra.w;
        acc[4] += xv * rb.x; acc[5] += xv * rb.y;
        acc[6] += xv * rb.z; acc[7] += xv * rb.w;
    }
#pragma unroll
    for (int e = 0; e < 8; e++) {
#pragma unroll
        for (int off = 16; off > 0; off >>= 1)
            acc[e] += __shfl_xor_sync(0xffffffffu, acc[e], off);
    }
    if (lane == 0) {
        float m = acc[0]; int idx = 0;
#pragma unroll
        for (int e = 1; e < 8; e++) if (acc[e] > m) { m = acc[e]; idx = e; }
        float s = 0.f;
#pragma unroll
        for (int e = 0; e < 8; e++) s += expf(acc[e] - m);
        g_expert[tok] = idx;
        g_prob[tok] = 1.f / s;
    }
}

__global__ void build_lists_kernel() {
    const int t = blockIdx.x * blockDim.x + threadIdx.x;
    if (t >= N_TOK) return;
    const int e = g_expert[t];
    const int pos = atomicAdd(&g_count[e], 1);
    g_list[e * N_TOK + pos] = t;
}

template<bool ENC>
__global__ void transpose_cvt_kernel(const float* __restrict__ in, int K, int N) {
    __half* outBase = ENC ? g_encT : g_decT;
    __shared__ __half tile[32][33];
    const float* ine = in + (size_t)blockIdx.z * K * N;
    __half* oute = outBase + (size_t)blockIdx.z * (size_t)K * N;
    const int n0 = blockIdx.x * 32, k0 = blockIdx.y * 32;
    const int tx = threadIdx.x, ty = threadIdx.y;
#pragma unroll
    for (int j = 0; j < 32; j += 8)
        tile[ty + j][tx] = __float2half_rn(ine[(size_t)(k0 + ty + j) * N + n0 + tx]);
    __syncthreads();
#pragma unroll
    for (int j = 0; j < 32; j += 8)
        oute[(size_t)(n0 + ty + j) * K + k0 + tx] = tile[tx][ty + j];
}

// ---------------- fp16 gather-GEMM: 128x128 tile, 64x32 warp tiles, 2 CTAs/SM ----------------
template<int KTOT, bool G1>
__global__ void __launch_bounds__(256, 2) sae_gemm_kernel(
    const float* __restrict__ pre_b, float* __restrict__ out)
{
    const int e = blockIdx.z;
    const int cnt = g_count[e];
    const int mBase = blockIdx.y * BM;
    if (mBase >= cnt) return;
    const int nBase = blockIdx.x * BN;
    const int* list = g_list + e * N_TOK;

    const __half* Asrc = G1 ? g_xh : g_latent;
    const __half* WT = (G1 ? g_encT : g_decT) + (size_t)e * (size_t)HDIM * DIN;

    extern __shared__ __align__(128) char smem[];
    const uint32_t sb = smem_u32(smem);

    const int tid = threadIdx.x, lane = tid & 31, warp = tid >> 5;
    const int wm = (warp >> 2) * 64, wn = (warp & 3) * 32;
    const int grp = lane >> 2, tig = lane & 3;

    // A staging: 2 threads per row, 32B each
    const int aRow = tid >> 1, sHalf = tid & 1;
    const int tokS = (mBase + aRow < cnt) ? list[mBase + aRow] : -1;
    const char* aSrcRow = (const char*)(Asrc + (size_t)(tokS >= 0 ? tokS : 0) * KTOT);
    const uint32_t aSz = (tokS >= 0) ? 16u : 0u;
    // B staging: 2 threads per n row, 32B each
    const char* bSrcRow = (const char*)(WT + (size_t)(nBase + aRow) * KTOT);

    const uint32_t aDstOff = (uint32_t)(aRow * PITCHB + sHalf * 32);
    const uint32_t bDstOff = (uint32_t)(A_BYTES + aRow * PITCHB + sHalf * 32);

    auto issue = [&](int c) {
        const uint32_t base = sb + (uint32_t)(c % STAGES) * STAGE_BYTES;
        const char* as = aSrcRow + c * 64 + sHalf * 32;
        CP16Z(base + aDstOff,      as,      aSz);
        CP16Z(base + aDstOff + 16, as + 16, aSz);
        const char* bs = bSrcRow + c * 64 + sHalf * 32;
        CP16(base + bDstOff,      bs);
        CP16(base + bDstOff + 16, bs + 16);
    };

    // ldmatrix per-thread address components (bytes, within stage)
    const uint32_t aLdsm = (uint32_t)((wm + (lane & 15)) * PITCHB + (lane >> 4) * 16);
    const uint32_t bLdsm = (uint32_t)(A_BYTES
                         + (wn + ((lane >> 4) << 3) + (lane & 7)) * PITCHB
                         + ((lane >> 3) & 1) * 16);

    float c[4][4][4];
#pragma unroll
    for (int mi = 0; mi < 4; mi++)
#pragma unroll
        for (int ni = 0; ni < 4; ni++)
#pragma unroll
            for (int j = 0; j < 4; j++) c[mi][ni][j] = 0.f;

    const int KT = KTOT / BK;      // G1: 24, G2: 64
#pragma unroll
    for (int s = 0; s < STAGES - 1; s++) {
        if (s < KT) issue(s);
        CP_COMMIT();
    }

    for (int kt = 0; kt < KT; ++kt) {
        CP_WAIT(STAGES - 2);
        __syncthreads();

        const uint32_t stageB = sb + (uint32_t)(kt % STAGES) * STAGE_BYTES;

        // issue next chunk's loads first (LSU pipe, overlaps below)
        if (kt + STAGES - 1 < KT) issue(kt + STAGES - 1);
        CP_COMMIT();

#pragma unroll
        for (int ks = 0; ks < BK; ks += 16) {
            const uint32_t kOff = (uint32_t)(ks * 2);
            uint32_t aF[4][4], bF[4][2];
#pragma unroll
            for (int mi = 0; mi < 4; mi++)
                ldsm4(aF[mi][0], aF[mi][1], aF[mi][2], aF[mi][3],
                      stageB + aLdsm + (uint32_t)(mi * 16 * PITCHB) + kOff);
#pragma unroll
            for (int p = 0; p < 2; p++)
                ldsm4(bF[2 * p][0], bF[2 * p][1], bF[2 * p + 1][0], bF[2 * p + 1][1],
                      stageB + bLdsm + (uint32_t)(p * 16 * PITCHB) + kOff);
#pragma unroll
            for (int mi = 0; mi < 4; mi++)
#pragma unroll
                for (int ni = 0; ni < 4; ni++)
                    mma_f16(c[mi][ni][0], c[mi][ni][1], c[mi][ni][2], c[mi][ni][3],
                            aF[mi][0], aF[mi][1], aF[mi][2], aF[mi][3],
                            bF[ni][0], bF[ni][1]);
        }
    }

    // ---- epilogue ----
#pragma unroll
    for (int mi = 0; mi < 4; mi++) {
        const int r0 = mBase + wm + mi * 16 + grp;
        const int r1 = r0 + 8;
        const int t0 = (r0 < cnt) ? list[r0] : -1;
        const int t1 = (r1 < cnt) ? list[r1] : -1;
        float p0 = 0.f, p1 = 0.f;
        if (!G1) {
            p0 = (t0 >= 0) ? g_prob[t0] : 0.f;
            p1 = (t1 >= 0) ? g_prob[t1] : 0.f;
        }
#pragma unroll
        for (int ni = 0; ni < 4; ni++) {
            const int col = nBase + wn + ni * 8 + tig * 2;
            if (G1) {
                if (t0 >= 0) {
                    __half2 v = __floats2half2_rn(fmaxf(c[mi][ni][0], 0.f), fmaxf(c[mi][ni][1], 0.f));
                    *(__half2*)(g_latent + (size_t)t0 * HDIM + col) = v;
                }
                if (t1 >= 0) {
                    __half2 v = __floats2half2_rn(fmaxf(c[mi][ni][2], 0.f), fmaxf(c[mi][ni][3], 0.f));
                    *(__half2*)(g_latent + (size_t)t1 * HDIM + col) = v;
                }
            } else {
                const float pb0 = __ldg(pre_b + col), pb1 = __ldg(pre_b + col + 1);
                if (t0 >= 0) {
                    float2 v = make_float2(p0 * c[mi][ni][0] + pb0, p0 * c[mi][ni][1] + pb1);
                    *(float2*)(out + (size_t)t0 * DIN + col) = v;
                }
                if (t1 >= 0) {
                    float2 v = make_float2(p1 * c[mi][ni][2] + pb0, p1 * c[mi][ni][3] + pb1);
                    *(float2*)(out + (size_t)t1 * DIN + col) = v;
                }
            }
        }
    }
}

// ---------------- launcher ----------------
extern "C" void kernel_launch(void* const* d_in, const int* in_sizes, int n_in,
                              void* d_out, int out_size) {
    const float* x        = (const float*)d_in[0];
    const float* pre_b    = (const float*)d_in[1];
    const float* enc      = (const float*)d_in[2];
    const float* dec      = (const float*)d_in[3];
    const float* router_b = (const float*)d_in[4];
    const float* router   = (const float*)d_in[5];
    float* out = (float*)d_out;

    cudaFuncSetAttribute(sae_gemm_kernel<DIN, true>,
                         cudaFuncAttributeMaxDynamicSharedMemorySize, SMEM_BYTES);
    cudaFuncSetAttribute(sae_gemm_kernel<HDIM, false>,
                         cudaFuncAttributeMaxDynamicSharedMemorySize, SMEM_BYTES);

    dim3 tb(32, 8);
    // gemm1 kept in ncu capture slot (#4).
    router_kernel<<<N_TOK / 8, 256>>>(x, router_b, router);                     // 1
    build_lists_kernel<<<N_TOK / 256, 256>>>();                                 // 2
    transpose_cvt_kernel<true ><<<dim3(HDIM / 32, DIN / 32, NEXP), tb>>>(enc, DIN, HDIM);  // 3
    dim3 g1(HDIM / BN, N_TOK / BM, NEXP);   // (16, 128, 8)
    sae_gemm_kernel<DIN, true><<<g1, 256, SMEM_BYTES>>>(pre_b, out);            // 4 (profiled)
    transpose_cvt_kernel<false><<<dim3(DIN / 32, HDIM / 32, NEXP), tb>>>(dec, HDIM, DIN);  // 5
    dim3 g2(DIN / BN, N_TOK / BM, NEXP);    // (6, 128, 8)
    sae_gemm_kernel<HDIM, false><<<g2, 256, SMEM_BYTES>>>(pre_b, out);          // 6
}

// round 15
// speedup vs baseline: 1.3729x; 1.2124x over previous
#include <cuda_runtime.h>
#include <cuda_fp16.h>
#include <cstdint>

#define N_TOK 16384
#define DIN   768
#define NEXP  8
#define HDIM  2048

#define BM 128
#define BN 128
#define BK 32
#define NTHR 512
#define PITCH 40              // smem row pitch in halfs
#define PITCHB (PITCH * 2)    // 80 bytes

#define A_BYTES (BM * PITCHB)               // 10240
#define B_BYTES (BN * PITCHB)               // 10240
#define STAGE_BYTES (A_BYTES + B_BYTES)     // 20480
#define STAGES 3
#define SMEM_BYTES (STAGES * STAGE_BYTES)   // 61440 per CTA (x2 CTAs = 120KB/SM)

// ---------------- device scratch (referenced ONLY from device code) ----------------
__device__ __align__(256) int    g_count[NEXP];
__device__ __align__(256) int    g_list[NEXP * N_TOK];
__device__ __align__(256) int    g_expert[N_TOK];
__device__ __align__(256) float  g_prob[N_TOK];
__device__ __align__(256) __half g_xh[(size_t)N_TOK * DIN];
__device__ __align__(256) __half g_encT[(size_t)NEXP * HDIM * DIN];  // [e][n][k]
__device__ __align__(256) __half g_decT[(size_t)NEXP * DIN * HDIM];  // [e][n][k]
__device__ __align__(256) __half g_latent[(size_t)N_TOK * HDIM];

// ---------------- asm helpers ----------------
__device__ __forceinline__ uint32_t smem_u32(const void* p) {
    uint32_t a;
    asm("{ .reg .u64 t; cvta.to.shared.u64 t, %1; cvt.u32.u64 %0, t; }" : "=r"(a) : "l"(p));
    return a;
}
#define CP16(dst, src) \
    asm volatile("cp.async.cg.shared.global [%0], [%1], 16;" :: "r"(dst), "l"(src) : "memory")
#define CP16Z(dst, src, sz) \
    asm volatile("cp.async.cg.shared.global [%0], [%1], 16, %2;" :: "r"(dst), "l"(src), "r"(sz) : "memory")
#define CP_COMMIT() asm volatile("cp.async.commit_group;" ::: "memory")
#define CP_WAIT(n)  asm volatile("cp.async.wait_group %0;" :: "n"(n) : "memory")

__device__ __forceinline__ void ldsm4(uint32_t& r0, uint32_t& r1, uint32_t& r2, uint32_t& r3,
                                      uint32_t addr) {
    asm volatile("ldmatrix.sync.aligned.m8n8.x4.shared.b16 {%0,%1,%2,%3}, [%4];"
                 : "=r"(r0), "=r"(r1), "=r"(r2), "=r"(r3) : "r"(addr));
}
__device__ __forceinline__ void mma_f16(float& c0, float& c1, float& c2, float& c3,
                                        uint32_t a0, uint32_t a1, uint32_t a2, uint32_t a3,
                                        uint32_t b0, uint32_t b1) {
    asm volatile("mma.sync.aligned.m16n8k16.row.col.f32.f16.f16.f32 "
                 "{%0,%1,%2,%3}, {%4,%5,%6,%7}, {%8,%9}, {%0,%1,%2,%3};\n"
                 : "+f"(c0), "+f"(c1), "+f"(c2), "+f"(c3)
                 : "r"(a0), "r"(a1), "r"(a2), "r"(a3), "r"(b0), "r"(b1));
}

// ---------------- prologue kernels ----------------
__global__ void router_kernel(const float* __restrict__ x,
                              const float* __restrict__ router_b,
                              const float* __restrict__ router) {
    if (blockIdx.x == 0 && threadIdx.x < NEXP) g_count[threadIdx.x] = 0;
    const int warp = threadIdx.x >> 5, lane = threadIdx.x & 31;
    const int tok = blockIdx.x * 8 + warp;
    float acc[8];
#pragma unroll
    for (int e = 0; e < 8; e++) acc[e] = 0.f;
    const float* xr = x + (size_t)tok * DIN;
    __half* xh = g_xh + (size_t)tok * DIN;
    for (int d = lane; d < DIN; d += 32) {
        const float xraw = xr[d];
        xh[d] = __float2half_rn(xraw);
        float xv = xraw - router_b[d];
        float4 ra = *(const float4*)(router + d * 8);
        float4 rb = *(const float4*)(router + d * 8 + 4);
        acc[0] += xv * ra.x; acc[1] += xv * ra.y;
        acc[2] += xv * ra.z; acc[3] += xv * ra.w;
        acc[4] += xv * rb.x; acc[5] += xv * rb.y;
        acc[6] += xv * rb.z; acc[7] += xv * rb.w;
    }
#pragma unroll
    for (int e = 0; e < 8; e++) {
#pragma unroll
        for (int off = 16; off > 0; off >>= 1)
            acc[e] += __shfl_xor_sync(0xffffffffu, acc[e], off);
    }
    if (lane == 0) {
        float m = acc[0]; int idx = 0;
#pragma unroll
        for (int e = 1; e < 8; e++) if (acc[e] > m) { m = acc[e]; idx = e; }
        float s = 0.f;
#pragma unroll
        for (int e = 0; e < 8; e++) s += expf(acc[e] - m);
        g_expert[tok] = idx;
        g_prob[tok] = 1.f / s;
    }
}

__global__ void build_lists_kernel() {
    const int t = blockIdx.x * blockDim.x + threadIdx.x;
    if (t >= N_TOK) return;
    const int e = g_expert[t];
    const int pos = atomicAdd(&g_count[e], 1);
    g_list[e * N_TOK + pos] = t;
}

template<bool ENC>
__global__ void transpose_cvt_kernel(const float* __restrict__ in, int K, int N) {
    __half* outBase = ENC ? g_encT : g_decT;
    __shared__ __half tile[32][33];
    const float* ine = in + (size_t)blockIdx.z * K * N;
    __half* oute = outBase + (size_t)blockIdx.z * (size_t)K * N;
    const int n0 = blockIdx.x * 32, k0 = blockIdx.y * 32;
    const int tx = threadIdx.x, ty = threadIdx.y;
#pragma unroll
    for (int j = 0; j < 32; j += 8)
        tile[ty + j][tx] = __float2half_rn(ine[(size_t)(k0 + ty + j) * N + n0 + tx]);
    __syncthreads();
#pragma unroll
    for (int j = 0; j < 32; j += 8)
        oute[(size_t)(n0 + ty + j) * K + k0 + tx] = tile[tx][ty + j];
}

// ---------------- fp16 gather-GEMM: 128x128 tile, 32x32 warp tiles, 512 thr, 2 CTAs/SM ----------------
template<int KTOT, bool G1>
__global__ void __launch_bounds__(NTHR, 2) sae_gemm_kernel(
    const float* __restrict__ pre_b, float* __restrict__ out)
{
    const int e = blockIdx.z;
    const int cnt = g_count[e];
    const int mBase = blockIdx.y * BM;
    if (mBase >= cnt) return;
    const int nBase = blockIdx.x * BN;
    const int* list = g_list + e * N_TOK;

    const __half* Asrc = G1 ? g_xh : g_latent;
    const __half* WT = (G1 ? g_encT : g_decT) + (size_t)e * (size_t)HDIM * DIN;

    extern __shared__ __align__(128) char smem[];
    const uint32_t sb = smem_u32(smem);

    const int tid = threadIdx.x, lane = tid & 31, warp = tid >> 5;
    const int wm = (warp >> 2) * 32, wn = (warp & 3) * 32;
    const int grp = lane >> 2, tig = lane & 3;

    // staging: 4 threads per row, 16B each (A and B both 128 rows x 64B)
    const int sRow = tid >> 2, sQ = tid & 3;
    const int tokS = (mBase + sRow < cnt) ? list[mBase + sRow] : -1;
    const char* aSrcRow = (const char*)(Asrc + (size_t)(tokS >= 0 ? tokS : 0) * KTOT);
    const uint32_t aSz = (tokS >= 0) ? 16u : 0u;
    const char* bSrcRow = (const char*)(WT + (size_t)(nBase + sRow) * KTOT);

    const uint32_t aDstOff = (uint32_t)(sRow * PITCHB + sQ * 16);
    const uint32_t bDstOff = (uint32_t)(A_BYTES + sRow * PITCHB + sQ * 16);

    auto issue = [&](int c) {
        const uint32_t base = sb + (uint32_t)(c % STAGES) * STAGE_BYTES;
        CP16Z(base + aDstOff, aSrcRow + c * 64 + sQ * 16, aSz);
        CP16(base + bDstOff, bSrcRow + c * 64 + sQ * 16);
    };

    // ldmatrix per-thread address components (bytes, within stage)
    const uint32_t aLdsm = (uint32_t)((wm + (lane & 15)) * PITCHB + (lane >> 4) * 16);
    const uint32_t bLdsm = (uint32_t)(A_BYTES
                         + (wn + ((lane >> 4) << 3) + (lane & 7)) * PITCHB
                         + ((lane >> 3) & 1) * 16);

    float c[2][4][4];
#pragma unroll
    for (int mi = 0; mi < 2; mi++)
#pragma unroll
        for (int ni = 0; ni < 4; ni++)
#pragma unroll
            for (int j = 0; j < 4; j++) c[mi][ni][j] = 0.f;

    const int KT = KTOT / BK;      // G1: 24, G2: 64
#pragma unroll
    for (int s = 0; s < STAGES - 1; s++) {
        if (s < KT) issue(s);
        CP_COMMIT();
    }

    for (int kt = 0; kt < KT; ++kt) {
        CP_WAIT(STAGES - 2);
        __syncthreads();

        const uint32_t stageB = sb + (uint32_t)(kt % STAGES) * STAGE_BYTES;

        // next chunk's loads first (LSU pipe, overlaps below)
        if (kt + STAGES - 1 < KT) issue(kt + STAGES - 1);
        CP_COMMIT();

#pragma unroll
        for (int ks = 0; ks < BK; ks += 16) {
            const uint32_t kOff = (uint32_t)(ks * 2);
            uint32_t aF[2][4], bF[4][2];
#pragma unroll
            for (int mi = 0; mi < 2; mi++)
                ldsm4(aF[mi][0], aF[mi][1], aF[mi][2], aF[mi][3],
                      stageB + aLdsm + (uint32_t)(mi * 16 * PITCHB) + kOff);
#pragma unroll
            for (int p = 0; p < 2; p++)
                ldsm4(bF[2 * p][0], bF[2 * p][1], bF[2 * p + 1][0], bF[2 * p + 1][1],
                      stageB + bLdsm + (uint32_t)(p * 16 * PITCHB) + kOff);
#pragma unroll
            for (int mi = 0; mi < 2; mi++)
#pragma unroll
                for (int ni = 0; ni < 4; ni++)
                    mma_f16(c[mi][ni][0], c[mi][ni][1], c[mi][ni][2], c[mi][ni][3],
                            aF[mi][0], aF[mi][1], aF[mi][2], aF[mi][3],
                            bF[ni][0], bF[ni][1]);
        }
    }

    // ---- epilogue ----
#pragma unroll
    for (int mi = 0; mi < 2; mi++) {
        const int r0 = mBase + wm + mi * 16 + grp;
        const int r1 = r0 + 8;
        const int t0 = (r0 < cnt) ? list[r0] : -1;
        const int t1 = (r1 < cnt) ? list[r1] : -1;
        float p0 = 0.f, p1 = 0.f;
        if (!G1) {
            p0 = (t0 >= 0) ? g_prob[t0] : 0.f;
            p1 = (t1 >= 0) ? g_prob[t1] : 0.f;
        }
#pragma unroll
        for (int ni = 0; ni < 4; ni++) {
            const int col = nBase + wn + ni * 8 + tig * 2;
            if (G1) {
                if (t0 >= 0) {
                    __half2 v = __floats2half2_rn(fmaxf(c[mi][ni][0], 0.f), fmaxf(c[mi][ni][1], 0.f));
                    *(__half2*)(g_latent + (size_t)t0 * HDIM + col) = v;
                }
                if (t1 >= 0) {
                    __half2 v = __floats2half2_rn(fmaxf(c[mi][ni][2], 0.f), fmaxf(c[mi][ni][3], 0.f));
                    *(__half2*)(g_latent + (size_t)t1 * HDIM + col) = v;
                }
            } else {
                const float pb0 = __ldg(pre_b + col), pb1 = __ldg(pre_b + col + 1);
                if (t0 >= 0) {
                    float2 v = make_float2(p0 * c[mi][ni][0] + pb0, p0 * c[mi][ni][1] + pb1);
                    *(float2*)(out + (size_t)t0 * DIN + col) = v;
                }
                if (t1 >= 0) {
                    float2 v = make_float2(p1 * c[mi][ni][2] + pb0, p1 * c[mi][ni][3] + pb1);
                    *(float2*)(out + (size_t)t1 * DIN + col) = v;
                }
            }
        }
    }
}

// ---------------- launcher ----------------
extern "C" void kernel_launch(void* const* d_in, const int* in_sizes, int n_in,
                              void* d_out, int out_size) {
    const float* x        = (const float*)d_in[0];
    const float* pre_b    = (const float*)d_in[1];
    const float* enc      = (const float*)d_in[2];
    const float* dec      = (const float*)d_in[3];
    const float* router_b = (const float*)d_in[4];
    const float* router   = (const float*)d_in[5];
    float* out = (float*)d_out;

    cudaFuncSetAttribute(sae_gemm_kernel<DIN, true>,
                         cudaFuncAttributeMaxDynamicSharedMemorySize, SMEM_BYTES);
    cudaFuncSetAttribute(sae_gemm_kernel<HDIM, false>,
                         cudaFuncAttributeMaxDynamicSharedMemorySize, SMEM_BYTES);

    dim3 tb(32, 8);
    // gemm1 kept in ncu capture slot (#4).
    router_kernel<<<N_TOK / 8, 256>>>(x, router_b, router);                     // 1
    build_lists_kernel<<<N_TOK / 256, 256>>>();                                 // 2
    transpose_cvt_kernel<true ><<<dim3(HDIM / 32, DIN / 32, NEXP), tb>>>(enc, DIN, HDIM);  // 3
    dim3 g1(HDIM / BN, N_TOK / BM, NEXP);   // (16, 128, 8)
    sae_gemm_kernel<DIN, true><<<g1, NTHR, SMEM_BYTES>>>(pre_b, out);           // 4 (profiled)
    transpose_cvt_kernel<false><<<dim3(DIN / 32, HDIM / 32, NEXP), tb>>>(dec, HDIM, DIN);  // 5
    dim3 g2(DIN / BN, N_TOK / BM, NEXP);    // (6, 128, 8)
    sae_gemm_kernel<HDIM, false><<<g2, NTHR, SMEM_BYTES>>>(pre_b, out);         // 6
}